// round 12
// baseline (speedup 1.0000x reference)
#include <cuda_runtime.h>
#include <cuda_fp16.h>

#define N_NODES 400000
#define N_EDGES 6400000
#define N_GRAPHS 20000
#define F_IN 11
#define HID 32
#define CAP 64   // padded CSR row capacity; deg ~ Poisson(16), P(>=64) ~ 0

// ---------------- scratch (static device globals; no allocs) ----------------
__device__ __align__(16) float g_fA[(size_t)N_NODES * HID];   // layer-1 gather src (h1*dinv)
__device__ __align__(16) float g_fC[(size_t)N_NODES * HID];   // layer-2 gather src (h2*dinv)
__device__ float g_dinv[N_NODES];
__device__ int   g_cursor[N_NODES];                 // fill cursor; == deg after k_fill
__device__ int   g_csr_pad[(size_t)N_NODES * CAP];  // padded CSR (src indices)
__device__ __align__(16) float g_sums[(size_t)N_GRAPHS * HID];
__device__ float g_cnt[N_GRAPHS];

// ---------------- helpers ----------------
__device__ __forceinline__ void red_add_v4(float* p, float a, float b, float c, float d) {
    asm volatile("red.global.add.v4.f32 [%0], {%1,%2,%3,%4};"
                 :: "l"(p), "f"(a), "f"(b), "f"(c), "f"(d) : "memory");
}
__device__ __forceinline__ void red_add_f32(float* p, float v) {
    asm volatile("red.global.add.f32 [%0], %1;" :: "l"(p), "f"(v) : "memory");
}

// ---------------- init ----------------
__global__ void k_zero() {
    int t = blockIdx.x * blockDim.x + threadIdx.x;
    if (t < N_GRAPHS * HID) g_sums[t]   = 0.0f;
    if (t < N_GRAPHS)       g_cnt[t]    = 0.0f;
    if (t < N_NODES)        g_cursor[t] = 0;
}

// padded-CSR fill: 4 edges per thread, int4 reads of src/dst
__global__ void k_fill(const int* __restrict__ ei) {
    int t = blockIdx.x * blockDim.x + threadIdx.x;
    int e = t * 4;
    if (e >= N_EDGES) return;
    const int4 s = *(const int4*)&ei[e];
    const int4 d = *(const int4*)&ei[N_EDGES + e];
    g_csr_pad[(size_t)d.x * CAP + atomicAdd(&g_cursor[d.x], 1)] = s.x;
    g_csr_pad[(size_t)d.y * CAP + atomicAdd(&g_cursor[d.y], 1)] = s.y;
    g_csr_pad[(size_t)d.z * CAP + atomicAdd(&g_cursor[d.z], 1)] = s.z;
    g_csr_pad[(size_t)d.w * CAP + atomicAdd(&g_cursor[d.w], 1)] = s.w;
}

// ---------------- layer-1 node GEMM + dinv: g_fA = (x @ W1) * dinv ----------------
__global__ void k_gemm1(const float* __restrict__ x, const float* __restrict__ W1) {
    int warp = (blockIdx.x * blockDim.x + threadIdx.x) >> 5;
    int lane = threadIdx.x & 31;
    if (warp >= N_NODES) return;
    float xi = (lane < F_IN) ? x[warp * F_IN + lane] : 0.0f;
    float acc = 0.0f;
#pragma unroll
    for (int k = 0; k < F_IN; k++)
        acc = fmaf(__shfl_sync(0xffffffffu, xi, k), W1[k * HID + lane], acc);
    int deg = g_cursor[warp];                         // broadcast load
    float di = rsqrtf((float)(deg + 1));              // +1 self-loop
    if (lane == 0) g_dinv[warp] = di;
    g_fA[(size_t)warp * HID + lane] = acc * di;
}

// ---------------- fused: aggr L1 (4 nodes/warp) + bias + relu + GEMM2 -> g_fC ----
// 8-lane group g owns node warp*4+g; lane q=lane&7 covers features 4q..4q+3 (float4).
// Warp-uniform degree loop, 8x unroll, coalesced index prefetch; W2 in smem.
__global__ void __launch_bounds__(256, 6)
k_aggr_gemm2(const float* __restrict__ b1, const float* __restrict__ W2) {
    __shared__ float sW2[HID * HID];
    for (int i = threadIdx.x; i < HID * HID; i += 256) sW2[i] = W2[i];
    __syncthreads();

    const unsigned FULL = 0xffffffffu;
    int warp = (blockIdx.x * blockDim.x + threadIdx.x) >> 5;
    int lane = threadIdx.x & 31;
    if (warp * 4 >= N_NODES) return;
    int q = lane & 7;
    int lb = lane & 24;                 // group base lane
    int node = warp * 4 + (lane >> 3);

    size_t beg = (size_t)node * CAP;
    int deg = g_cursor[node];
    float di = g_dinv[node];

    // warp-max degree (deg uniform within 8-lane group; xor 8,16 spans groups)
    int maxdeg = deg;
    maxdeg = max(maxdeg, __shfl_xor_sync(FULL, maxdeg, 8));
    maxdeg = max(maxdeg, __shfl_xor_sync(FULL, maxdeg, 16));
    maxdeg = min(maxdeg, CAP);

    float a0, a1, a2, a3;
    {   // self-loop row
        float4 p = *(const float4*)&g_fA[(size_t)node * HID + q * 4];
        a0 = p.x; a1 = p.y; a2 = p.z; a3 = p.w;
    }

    for (int t = 0; t < maxdeg; t += 8) {
        int pre = __ldg(&g_csr_pad[beg + t + q]);   // lane q: slot t+q of own row (<= 63)
#pragma unroll
        for (int u = 0; u < 8; u++) {
            int idx = __shfl_sync(FULL, pre, lb + u);
            if (t + u < deg) {
                float4 p = *(const float4*)&g_fA[(size_t)idx * HID + q * 4];
                a0 += p.x; a1 += p.y; a2 += p.z; a3 += p.w;
            }
        }
    }

    // hoisted: v = relu(agg*di + b1)  (lane q owns features 4q..4q+3)
    float4 bq = ((const float4*)b1)[q];
    float v0 = fmaxf(fmaf(a0, di, bq.x), 0.0f);
    float v1 = fmaxf(fmaf(a1, di, bq.y), 0.0f);
    float v2 = fmaxf(fmaf(a2, di, bq.z), 0.0f);
    float v3 = fmaxf(fmaf(a3, di, bq.w), 0.0f);

    float di0 = __shfl_sync(FULL, di, 0);
    float di1 = __shfl_sync(FULL, di, 8);
    float di2 = __shfl_sync(FULL, di, 16);
    float di3 = __shfl_sync(FULL, di, 24);

    float o0 = 0.0f, o1 = 0.0f, o2 = 0.0f, o3 = 0.0f;
#pragma unroll
    for (int k = 0; k < HID; k++) {
        float vr = (k & 3) == 0 ? v0 : (k & 3) == 1 ? v1 : (k & 3) == 2 ? v2 : v3;
        int sl = k >> 2;
        float w = sW2[k * HID + lane];
        o0 = fmaf(__shfl_sync(FULL, vr, sl),      w, o0);
        o1 = fmaf(__shfl_sync(FULL, vr, 8 + sl),  w, o1);
        o2 = fmaf(__shfl_sync(FULL, vr, 16 + sl), w, o2);
        o3 = fmaf(__shfl_sync(FULL, vr, 24 + sl), w, o3);
    }
    size_t base = (size_t)(warp * 4) * HID + lane;
    g_fC[base + 0 * HID] = o0 * di0;
    g_fC[base + 1 * HID] = o1 * di1;
    g_fC[base + 2 * HID] = o2 * di2;
    g_fC[base + 3 * HID] = o3 * di3;
}

// ---------------- fused: aggr L2 (4 nodes/warp) + pool ----------------
__global__ void __launch_bounds__(256, 6)
k_aggr_pool(const int* __restrict__ batch) {
    const unsigned FULL = 0xffffffffu;
    int warp = (blockIdx.x * blockDim.x + threadIdx.x) >> 5;
    int lane = threadIdx.x & 31;
    if (warp * 4 >= N_NODES) return;
    int q = lane & 7;
    int lb = lane & 24;
    int node = warp * 4 + (lane >> 3);

    size_t beg = (size_t)node * CAP;
    int deg = g_cursor[node];
    float di = g_dinv[node];

    int maxdeg = deg;
    maxdeg = max(maxdeg, __shfl_xor_sync(FULL, maxdeg, 8));
    maxdeg = max(maxdeg, __shfl_xor_sync(FULL, maxdeg, 16));
    maxdeg = min(maxdeg, CAP);

    float a0, a1, a2, a3;
    {
        float4 p = *(const float4*)&g_fC[(size_t)node * HID + q * 4];
        a0 = p.x; a1 = p.y; a2 = p.z; a3 = p.w;
    }

    for (int t = 0; t < maxdeg; t += 8) {
        int pre = __ldg(&g_csr_pad[beg + t + q]);
#pragma unroll
        for (int u = 0; u < 8; u++) {
            int idx = __shfl_sync(FULL, pre, lb + u);
            if (t + u < deg) {
                float4 p = *(const float4*)&g_fC[(size_t)idx * HID + q * 4];
                a0 += p.x; a1 += p.y; a2 += p.z; a3 += p.w;
            }
        }
    }

    int grp = batch[node];
    red_add_v4(&g_sums[(size_t)grp * HID + q * 4], a0 * di, a1 * di, a2 * di, a3 * di);
    if (q == 0) red_add_f32(&g_cnt[grp], 1.0f);
}

// ---------------- MLP head ----------------
__global__ void k_mlp(const float* __restrict__ b2,
                      const float* __restrict__ fcW1, const float* __restrict__ fcb1,
                      const float* __restrict__ fcW2, const float* __restrict__ fcb2,
                      float* __restrict__ out) {
    int warp = (blockIdx.x * blockDim.x + threadIdx.x) >> 5;
    int lane = threadIdx.x & 31;
    if (warp >= N_GRAPHS) return;
    float cnt = g_cnt[warp];
    float inv = 1.0f / fmaxf(cnt, 1.0f);
    // pooled = (sum(agg2) + cnt*b2) / max(cnt,1)  == mean(agg2 + b2)
    float p = (g_sums[(size_t)warp * HID + lane] + cnt * b2[lane]) * inv;
    float acc = fcb1[lane];
#pragma unroll
    for (int k = 0; k < HID; k++)
        acc = fmaf(__shfl_sync(0xffffffffu, p, k), fcW1[k * HID + lane], acc);
    acc = fmaxf(acc, 0.0f);
    float o = acc * fcW2[lane];
#pragma unroll
    for (int off = 16; off > 0; off >>= 1)
        o += __shfl_xor_sync(0xffffffffu, o, off);
    if (lane == 0) out[warp] = o + fcb2[0];
}

// ---------------- launch ----------------
extern "C" void kernel_launch(void* const* d_in, const int* in_sizes, int n_in,
                              void* d_out, int out_size) {
    const float* x     = (const float*)d_in[0];
    const int*   ei    = (const int*)  d_in[1];
    const int*   batch = (const int*)  d_in[2];
    const float* W1    = (const float*)d_in[3];
    const float* b1    = (const float*)d_in[4];
    const float* W2    = (const float*)d_in[5];
    const float* b2    = (const float*)d_in[6];
    const float* fcW1  = (const float*)d_in[7];
    const float* fcb1  = (const float*)d_in[8];
    const float* fcW2  = (const float*)d_in[9];
    const float* fcb2  = (const float*)d_in[10];
    float* out = (float*)d_out;

    const int TB = 256;
    const int edge4_grid = (N_EDGES / 4 + TB - 1) / TB;
    const int warp_grid  = (N_NODES * 32 + TB - 1) / TB;          // warp per node
    const int warp4_grid = ((N_NODES / 4) * 32 + TB - 1) / TB;    // warp per 4 nodes

    // launch order fixed so ncu (-s 5, incl. 2 harness launches) profiles k_aggr_gemm2
    k_zero      <<<(N_GRAPHS * HID + TB - 1) / TB, TB>>>();          // 0
    k_fill      <<<edge4_grid, TB>>>(ei);                            // 1
    k_gemm1     <<<warp_grid, TB>>>(x, W1);                          // 2
    k_aggr_gemm2<<<warp4_grid, TB>>>(b1, W2);                        // 3  <- profiled
    k_aggr_pool <<<warp4_grid, TB>>>(batch);                         // 4
    k_mlp       <<<(N_GRAPHS * 32 + TB - 1) / TB, TB>>>(b2, fcW1, fcb1, fcW2, fcb2, out);
}